// round 6
// baseline (speedup 1.0000x reference)
#include <cuda_runtime.h>
#include <cuda_bf16.h>

#define NN 16384      // nodes/edges (and bond_n rows A = 16384)
#define DD 128        // emb dim
// Only layer i = 2 matters: the reference loop does not feed h back.

#define NBLK 296      // 2 blocks per SM on 148 SMs, single wave

// Scratch (device globals — zero-initialized at module load)
__device__ float g_colw[NN];
__device__ float g_hn[(size_t)NN * DD];      // 8 MB
__device__ float g_mpartT[DD][128];          // m partials, contiguous per d
__device__ unsigned g_zc, g_zdone;           // k_all zero-flag + exit counter
__device__ unsigned g_mc, g_mdone;           // k_m grid-sync + exit counter

// ---------------------------------------------------------------------------
// k_all, 296 blocks (one wave @ 2/SM):
//   entry:           blocks 0..63 zero g_colw (flag-counter g_zc).
//   blocks [0,128):  GEMM h_n = relu(cat @ Wi_w[2].T + b) -> g_hn,
//                    then stream 51 rows of bond_n (row-contiguous).
//   blocks [128,296): stream 58-59 rows.
//   end of stream:   wait g_zc>=64 (instant), then REDG-atomicAdd the 16384
//                    register column partials into g_colw. No g_part buffer.
// ---------------------------------------------------------------------------
__global__ void __launch_bounds__(256, 2) k_all(
    const float* __restrict__ bn,
    const int* __restrict__ x, const int* __restrict__ ea,
    const float* __restrict__ aemb, const float* __restrict__ bemb,
    const float* __restrict__ Wi_w2, const float* __restrict__ Wi_b2)
{
    extern __shared__ float sm[];
    const int tid = threadIdx.x;
    const int bid = blockIdx.x;

    // ---- zero g_colw (blocks 0..63, 256 floats each) ----
    if (bid < 64) {
        g_colw[bid * 256 + tid] = 0.f;
        __syncthreads();
        if (tid == 0) { __threadfence(); atomicAdd(&g_zc, 1u); }
    }

    // ---- static row shares for the bond_n stream (sum = 16384) ----
    int start, cnt;
    if (bid < 128)          { start = bid * 51;                 cnt = 51; }
    else if (bid < 240)     { start = 6528  + (bid - 128) * 59; cnt = 59; }
    else                    { start = 13136 + (bid - 240) * 58; cnt = 58; }

    if (bid < 128) {
        // ---------------- GEMM phase ----------------
        float* w_s   = sm;                 // [64][129] = 33,024 B
        float* cat_s = sm + 64 * 129;      // [128][64] = 32,768 B
        __shared__ float bias_s[128];
        __shared__ int xi0[128], xi1[128], ei0[128], ei1[128];

        const int rowBase = bid * 128;
        if (tid < 128) {
            bias_s[tid] = Wi_b2[tid];
            int r = rowBase + tid;
            xi0[tid] = x[2 * r];  xi1[tid] = x[2 * r + 1];
            ei0[tid] = ea[2 * r]; ei1[tid] = ea[2 * r + 1];
        }
        __syncthreads();

        const int tx = tid & 15, ty = tid >> 4;
        float acc[8][8];
#pragma unroll
        for (int i = 0; i < 8; i++)
#pragma unroll
            for (int j = 0; j < 8; j++) acc[i][j] = 0.f;

        for (int kc = 0; kc < 256; kc += 64) {
            for (int idx = tid; idx < 8192; idx += 256) {
                int d = idx >> 6, kk = idx & 63;
                w_s[kk * 129 + d] = Wi_w2[d * 256 + kc + kk];
            }
            const bool atom = (kc < 128);
            const float* emb = atom ? aemb : bemb;
            for (int idx = tid; idx < 2048; idx += 256) {
                int row  = idx >> 4;
                int kloc = (idx & 15) * 4;
                int i0 = atom ? xi0[row] : ei0[row];
                int i1 = atom ? xi1[row] : ei1[row];
                int ko = atom ? (kc + kloc) : (kc - 128 + kloc);
                float4 v0 = *(const float4*)(emb + i0 * 128 + ko);
                float4 v1 = *(const float4*)(emb + i1 * 128 + ko);
                float4 s;
                s.x = v0.x + v1.x; s.y = v0.y + v1.y;
                s.z = v0.z + v1.z; s.w = v0.w + v1.w;
                *(float4*)(cat_s + row * 64 + kloc) = s;
            }
            __syncthreads();

#pragma unroll 8
            for (int kk = 0; kk < 64; kk++) {
                const float* wr = w_s + kk * 129;
                float b[8], a[8];
#pragma unroll
                for (int j = 0; j < 8; j++) b[j] = wr[tx + 16 * j];
#pragma unroll
                for (int i = 0; i < 8; i++) a[i] = cat_s[(ty + 16 * i) * 64 + kk];
#pragma unroll
                for (int i = 0; i < 8; i++)
#pragma unroll
                    for (int j = 0; j < 8; j++)
                        acc[i][j] = fmaf(a[i], b[j], acc[i][j]);
            }
            __syncthreads();
        }

        // bias + relu -> g_hn
#pragma unroll
        for (int i = 0; i < 8; i++) {
            int r = ty + 16 * i;
#pragma unroll
            for (int j = 0; j < 8; j++) {
                int d = tx + 16 * j;
                float v = acc[i][j] + bias_s[d];
                g_hn[(size_t)(rowBase + r) * 128 + d] = v > 0.f ? v : 0.f;
            }
        }
    }

    // ---------------- bond_n streaming (ALL blocks) ----------------
    float4 acc[16];
#pragma unroll
    for (int i = 0; i < 16; i++) acc[i] = make_float4(0.f, 0.f, 0.f, 0.f);

    for (int r = 0; r < cnt; r++) {
        const float4* rp = (const float4*)(bn + (size_t)(start + r) * NN) + tid;
#pragma unroll
        for (int i = 0; i < 16; i++) {
            float4 v = __ldcs(rp + i * 256);
            acc[i].x += v.x; acc[i].y += v.y; acc[i].z += v.z; acc[i].w += v.w;
        }
    }

    // wait for zeroing (finished ~150us ago; spin is instant)
    if (tid == 0) { while (atomicAdd(&g_zc, 0u) < 64u) __nanosleep(32); }
    __syncthreads();
    __threadfence();

    // spread-address REDG adds: column base = (tid + i*256)*4
#pragma unroll
    for (int i = 0; i < 16; i++) {
        int c = (tid + i * 256) * 4;
        atomicAdd(&g_colw[c + 0], acc[i].x);
        atomicAdd(&g_colw[c + 1], acc[i].y);
        atomicAdd(&g_colw[c + 2], acc[i].z);
        atomicAdd(&g_colw[c + 3], acc[i].w);
    }

    // exit: last block resets counters for next graph replay
    __syncthreads();
    if (tid == 0) {
        __threadfence();
        unsigned r = atomicAdd(&g_zdone, 1u);
        if (r == NBLK - 1u) { g_zc = 0u; __threadfence(); g_zdone = 0u; }
    }
}

// ---------------------------------------------------------------------------
// k_tail, 128 blocks (all co-resident -> internal grid-sync safe):
//   S1: m partial over own 128 rows (from g_hn) -> g_mpartT[d][bid]
//   sync
//   S2: redundant per-block m reduce (L2-hot 64KB) + mm = m@Wm^T + b
//   S3: out = relu(h_n + mm) for own rows (h_n L2-warm)
// ---------------------------------------------------------------------------
__global__ void __launch_bounds__(256) k_tail(const float* __restrict__ Wm_w2,
                                              const float* __restrict__ Wm_b2,
                                              float* __restrict__ out) {
    __shared__ float colw_s[128];
    __shared__ float red[256];
    __shared__ float mm_s[128];

    const int bid = blockIdx.x, tid = threadIdx.x;
    const int rowBase = bid * 128;
    const int d = tid & 127, half = tid >> 7;

    if (tid < 128) colw_s[tid] = g_colw[rowBase + tid];
    __syncthreads();

    // S1: m partial
    {
        float p = 0.f;
#pragma unroll 16
        for (int r = 0; r < 64; r++) {
            int row = half * 64 + r;
            p = fmaf(colw_s[row], g_hn[(size_t)(rowBase + row) * DD + d], p);
        }
        red[tid] = p;
    }
    __syncthreads();
    if (tid < 128) g_mpartT[tid][bid] = red[tid] + red[tid + 128];

    // grid-sync over 128 blocks
    __threadfence();
    __syncthreads();
    if (tid == 0) {
        atomicAdd(&g_mc, 1u);
        while (atomicAdd(&g_mc, 0u) < 128u) __nanosleep(32);
        __threadfence();
    }
    __syncthreads();

    // S2: redundant m reduce + mm GEMV
    if (tid < 128) {
        const float4* mp = (const float4*)g_mpartT[tid];
        float s = 0.f;
#pragma unroll 32
        for (int w = 0; w < 32; w++) {
            float4 v = __ldcg(mp + w);
            s += v.x + v.y + v.z + v.w;
        }
        red[tid] = s;        // red = m
    }
    __syncthreads();
    if (tid < 128) {
        float s = Wm_b2[tid];
        const float* row = Wm_w2 + tid * 128;
#pragma unroll 8
        for (int k = 0; k < 128; k++) s = fmaf(red[k], __ldg(row + k), s);
        mm_s[tid] = s;
    }
    __syncthreads();

    // S3: out = relu(h_n + mm), coalesced float4 (h_n L2-warm)
    {
        const float* hn = g_hn + (size_t)rowBase * 128;
        float4* ob = (float4*)(out + (size_t)rowBase * 128);
#pragma unroll 4
        for (int i = tid; i < 4096; i += 256) {
            int row = i >> 5, dg = (i & 31) * 4;
            float4 v = *(const float4*)(hn + row * 128 + dg);
            v.x = fmaxf(v.x + mm_s[dg + 0], 0.f);
            v.y = fmaxf(v.y + mm_s[dg + 1], 0.f);
            v.z = fmaxf(v.z + mm_s[dg + 2], 0.f);
            v.w = fmaxf(v.w + mm_s[dg + 3], 0.f);
            ob[i] = v;
        }
    }

    // reset counters for next graph replay
    __syncthreads();
    if (tid == 0) {
        unsigned r = atomicAdd(&g_mdone, 1u);
        if (r == 127u) { g_mc = 0u; __threadfence(); g_mdone = 0u; }
    }
}

// ---------------------------------------------------------------------------
extern "C" void kernel_launch(void* const* d_in, const int* in_sizes, int n_in,
                              void* d_out, int out_size) {
    const int*   x    = (const int*)d_in[0];
    const int*   ea   = (const int*)d_in[1];
    const float* bn   = (const float*)d_in[2];
    const float* aemb = (const float*)d_in[3];
    const float* bemb = (const float*)d_in[4];
    const float* Wi_w = (const float*)d_in[5];
    const float* Wi_b = (const float*)d_in[6];
    const float* Wm_w = (const float*)d_in[7];
    const float* Wm_b = (const float*)d_in[8];

    // Only the last layer (i = 2) affects the output.
    const float* Wi_w2 = Wi_w + 2 * 128 * 256;
    const float* Wi_b2 = Wi_b + 2 * 128;
    const float* Wm_w2 = Wm_w + 2 * 128 * 128;
    const float* Wm_b2 = Wm_b + 2 * 128;

    const int smem = (64 * 129 + 128 * 64) * (int)sizeof(float);  // 65,792 B
    static bool attr_set = false;
    if (!attr_set) {
        cudaFuncSetAttribute(k_all, cudaFuncAttributeMaxDynamicSharedMemorySize, smem);
        attr_set = true;
    }

    k_all<<<NBLK, 256, smem>>>(bn, x, ea, aemb, bemb, Wi_w2, Wi_b2);
    k_tail<<<128, 256>>>(Wm_w2, Wm_b2, (float*)d_out);
}